// round 1
// baseline (speedup 1.0000x reference)
#include <cuda_runtime.h>
#include <cuda_bf16.h>

// EdgewiseEnergySum: out[c] += eng[e] * scales[species[c], species[n]] * 0.125
// edge_index: [2, E] int32 (row 0 = centers, row 1 = neighbors)
// edge_eng:   [E] float32
// atom_type:  [N] int32
// per_edge_scales: [8, 8] float32
// out: [N] float32

#define N_NODES 100000
#define N_EDGES 6400000
#define FACTOR 0.125f   // 1/sqrt(64)

__global__ void zero_out_kernel(float* __restrict__ out, int n) {
    int i = blockIdx.x * blockDim.x + threadIdx.x;
    if (i < n) out[i] = 0.0f;
}

__global__ __launch_bounds__(256) void edgewise_scatter_kernel(
    const int* __restrict__ centers,
    const int* __restrict__ neighbors,
    const float* __restrict__ eng,
    const int* __restrict__ species,
    const float* __restrict__ scales,
    float* __restrict__ out)
{
    __shared__ float s_sc[64];
    if (threadIdx.x < 64) s_sc[threadIdx.x] = scales[threadIdx.x];
    __syncthreads();

    int i = blockIdx.x * blockDim.x + threadIdx.x;   // i indexes groups of 4 edges
    // E/4 = 1,600,000 threads exactly; grid sized to match, no bounds check needed
    int4   c4 = reinterpret_cast<const int4*>(centers)[i];
    int4   n4 = reinterpret_cast<const int4*>(neighbors)[i];
    float4 e4 = reinterpret_cast<const float4*>(eng)[i];

    // species gathers (L2-resident, 400KB table)
    int sc0 = species[c4.x], sn0 = species[n4.x];
    int sc1 = species[c4.y], sn1 = species[n4.y];
    int sc2 = species[c4.z], sn2 = species[n4.z];
    int sc3 = species[c4.w], sn3 = species[n4.w];

    float v0 = e4.x * s_sc[(sc0 << 3) | sn0] * FACTOR;
    float v1 = e4.y * s_sc[(sc1 << 3) | sn1] * FACTOR;
    float v2 = e4.z * s_sc[(sc2 << 3) | sn2] * FACTOR;
    float v3 = e4.w * s_sc[(sc3 << 3) | sn3] * FACTOR;

    atomicAdd(&out[c4.x], v0);
    atomicAdd(&out[c4.y], v1);
    atomicAdd(&out[c4.z], v2);
    atomicAdd(&out[c4.w], v3);
}

extern "C" void kernel_launch(void* const* d_in, const int* in_sizes, int n_in,
                              void* d_out, int out_size) {
    const int*   edge_index = (const int*)d_in[0];      // [2, E]
    const float* edge_eng   = (const float*)d_in[1];    // [E]
    const int*   atom_type  = (const int*)d_in[2];      // [N]
    const float* scales     = (const float*)d_in[3];    // [8, 8]
    float* out = (float*)d_out;

    const int E = in_sizes[0] / 2;   // 6,400,000
    const int N = out_size;          // 100,000

    // zero the poisoned output buffer
    zero_out_kernel<<<(N + 255) / 256, 256>>>(out, N);

    const int* centers   = edge_index;
    const int* neighbors = edge_index + E;

    int groups = E / 4;              // 1,600,000
    edgewise_scatter_kernel<<<groups / 256, 256>>>(
        centers, neighbors, edge_eng, atom_type, scales, out);
}

// round 2
// speedup vs baseline: 1.4006x; 1.4006x over previous
#include <cuda_runtime.h>
#include <cuda_bf16.h>

// EdgewiseEnergySum: out[c] += eng[e] * scales[species[c], species[n]] * 0.125
// Strategy: species table (100K nodes, values 0..7) packed to uint8 and staged
// in SHARED memory per block -> random gathers become LDS instead of L2 sector
// traffic (was ~410MB of L2 sectors). Atomics stay as spread REDG to L2.

#define N_NODES_PAD 100096          // padded to multiple of 16 for uint4 copies
#define N_EDGES     6400000

__device__ unsigned char g_species[N_NODES_PAD];

// Kernel 1: zero the poisoned output and pack species to uint8
__global__ void prep_kernel(const int* __restrict__ atom_type,
                            float* __restrict__ out, int n) {
    int i = blockIdx.x * blockDim.x + threadIdx.x;
    if (i < n) {
        out[i] = 0.0f;
        g_species[i] = (unsigned char)atom_type[i];
    }
}

// Kernel 2: persistent-style scatter. Each block stages the full 100KB species
// table in dynamic shared memory, then grid-strides over groups of 4 edges.
__global__ __launch_bounds__(512) void edgewise_scatter_kernel(
    const int* __restrict__ centers,
    const int* __restrict__ neighbors,
    const float* __restrict__ eng,
    const float* __restrict__ scales,
    float* __restrict__ out)
{
    __shared__ float s_sc[64];
    extern __shared__ unsigned char s_species[];

    if (threadIdx.x < 64) s_sc[threadIdx.x] = scales[threadIdx.x] * 0.125f;

    // cooperative 128-bit copy of the species table: 100096/16 = 6256 uint4
    {
        const uint4* src = reinterpret_cast<const uint4*>(g_species);
        uint4*       dst = reinterpret_cast<uint4*>(s_species);
        for (int i = threadIdx.x; i < N_NODES_PAD / 16; i += blockDim.x)
            dst[i] = src[i];
    }
    __syncthreads();

    const int ngroups = N_EDGES / 4;           // 1,600,000
    const int stride  = gridDim.x * blockDim.x;

    for (int i = blockIdx.x * blockDim.x + threadIdx.x; i < ngroups; i += stride) {
        int4   c4 = reinterpret_cast<const int4*>(centers)[i];
        int4   n4 = reinterpret_cast<const int4*>(neighbors)[i];
        float4 e4 = reinterpret_cast<const float4*>(eng)[i];

        float v0 = e4.x * s_sc[(s_species[c4.x] << 3) | s_species[n4.x]];
        float v1 = e4.y * s_sc[(s_species[c4.y] << 3) | s_species[n4.y]];
        float v2 = e4.z * s_sc[(s_species[c4.z] << 3) | s_species[n4.z]];
        float v3 = e4.w * s_sc[(s_species[c4.w] << 3) | s_species[n4.w]];

        atomicAdd(&out[c4.x], v0);
        atomicAdd(&out[c4.y], v1);
        atomicAdd(&out[c4.z], v2);
        atomicAdd(&out[c4.w], v3);
    }
}

extern "C" void kernel_launch(void* const* d_in, const int* in_sizes, int n_in,
                              void* d_out, int out_size) {
    const int*   edge_index = (const int*)d_in[0];      // [2, E]
    const float* edge_eng   = (const float*)d_in[1];    // [E]
    const int*   atom_type  = (const int*)d_in[2];      // [N]
    const float* scales     = (const float*)d_in[3];    // [8, 8]
    float* out = (float*)d_out;

    const int E = in_sizes[0] / 2;   // 6,400,000
    const int N = out_size;          // 100,000

    prep_kernel<<<(N + 255) / 256, 256>>>(atom_type, out, N);

    const int* centers   = edge_index;
    const int* neighbors = edge_index + E;

    const int smem_bytes = N_NODES_PAD;  // 100,096 bytes dynamic shared
    static int attr_set = 0;
    if (!attr_set) {
        cudaFuncSetAttribute(edgewise_scatter_kernel,
                             cudaFuncAttributeMaxDynamicSharedMemorySize,
                             smem_bytes);
        attr_set = 1;
    }

    // 2 blocks per SM (2 x ~100KB shared <= 227KB/SM), 148 SMs
    edgewise_scatter_kernel<<<296, 512, smem_bytes>>>(
        centers, neighbors, edge_eng, scales, out);
}

// round 3
// speedup vs baseline: 1.5202x; 1.0853x over previous
#include <cuda_runtime.h>
#include <cuda_bf16.h>

// EdgewiseEnergySum: out[c] += eng[e] * scales[species[c], species[n]] * 0.125
// Species values are 0..7 (3 bits) -> pack TWO nodes per byte. The 100K-node
// table becomes 50KB, letting 4 CTAs/SM stay resident (was 2 with the 100KB
// byte table) -> ~2x latency hiding for the LDG->LDS->REDG chains.

#define N_NODES   100000
#define N_BYTES   50000            // 2 species per byte; 50000 % 16 == 0
#define N_EDGES   6400000

__device__ unsigned char g_species4[N_BYTES];

// Kernel 1: zero the poisoned output and pack species into nibbles.
__global__ void prep_kernel(const int* __restrict__ atom_type,
                            float* __restrict__ out, int n) {
    int i = blockIdx.x * blockDim.x + threadIdx.x;
    if (i < n) out[i] = 0.0f;
    if (i < N_BYTES) {
        unsigned lo = (unsigned)atom_type[2 * i];
        unsigned hi = (unsigned)atom_type[2 * i + 1];
        g_species4[i] = (unsigned char)(lo | (hi << 4));
    }
}

__device__ __forceinline__ int nib(const unsigned char* t, int idx) {
    unsigned b = t[idx >> 1];
    return (int)((b >> ((idx & 1) << 2)) & 7u);
}

// Kernel 2: persistent scatter, 4 CTAs/SM, nibble-packed species in smem.
__global__ __launch_bounds__(512, 4) void edgewise_scatter_kernel(
    const int* __restrict__ centers,
    const int* __restrict__ neighbors,
    const float* __restrict__ eng,
    const float* __restrict__ scales,
    float* __restrict__ out)
{
    __shared__ float s_sc[64];
    extern __shared__ unsigned char s_sp[];

    if (threadIdx.x < 64) s_sc[threadIdx.x] = scales[threadIdx.x] * 0.125f;

    // cooperative 128-bit copy: 50000/16 = 3125 uint4
    {
        const uint4* src = reinterpret_cast<const uint4*>(g_species4);
        uint4*       dst = reinterpret_cast<uint4*>(s_sp);
        for (int i = threadIdx.x; i < N_BYTES / 16; i += blockDim.x)
            dst[i] = src[i];
    }
    __syncthreads();

    const int ngroups = N_EDGES / 4;           // 1,600,000
    const int stride  = gridDim.x * blockDim.x;

    for (int i = blockIdx.x * blockDim.x + threadIdx.x; i < ngroups; i += stride) {
        int4   c4 = reinterpret_cast<const int4*>(centers)[i];
        int4   n4 = reinterpret_cast<const int4*>(neighbors)[i];
        float4 e4 = reinterpret_cast<const float4*>(eng)[i];

        float v0 = e4.x * s_sc[(nib(s_sp, c4.x) << 3) | nib(s_sp, n4.x)];
        float v1 = e4.y * s_sc[(nib(s_sp, c4.y) << 3) | nib(s_sp, n4.y)];
        float v2 = e4.z * s_sc[(nib(s_sp, c4.z) << 3) | nib(s_sp, n4.z)];
        float v3 = e4.w * s_sc[(nib(s_sp, c4.w) << 3) | nib(s_sp, n4.w)];

        atomicAdd(&out[c4.x], v0);
        atomicAdd(&out[c4.y], v1);
        atomicAdd(&out[c4.z], v2);
        atomicAdd(&out[c4.w], v3);
    }
}

extern "C" void kernel_launch(void* const* d_in, const int* in_sizes, int n_in,
                              void* d_out, int out_size) {
    const int*   edge_index = (const int*)d_in[0];      // [2, E]
    const float* edge_eng   = (const float*)d_in[1];    // [E]
    const int*   atom_type  = (const int*)d_in[2];      // [N]
    const float* scales     = (const float*)d_in[3];    // [8, 8]
    float* out = (float*)d_out;

    const int E = in_sizes[0] / 2;   // 6,400,000
    const int N = out_size;          // 100,000

    prep_kernel<<<(N + 255) / 256, 256>>>(atom_type, out, N);

    const int* centers   = edge_index;
    const int* neighbors = edge_index + E;

    const int smem_bytes = N_BYTES;  // 50,000 bytes dynamic shared
    static int attr_set = 0;
    if (!attr_set) {
        cudaFuncSetAttribute(edgewise_scatter_kernel,
                             cudaFuncAttributeMaxDynamicSharedMemorySize,
                             smem_bytes);
        attr_set = 1;
    }

    // 4 blocks per SM x 148 SMs = 592 blocks, 512 threads each
    edgewise_scatter_kernel<<<592, 512, smem_bytes>>>(
        centers, neighbors, edge_eng, scales, out);
}